// round 2
// baseline (speedup 1.0000x reference)
#include <cuda_runtime.h>

// PointNet++ SA layer: FPS -> radius ball query (K nearest within r) -> MLP(67->128->128) -> max agg
// B=8, N_PER=4096, N_SAMPLE=1024, K=64, C_IN=64, H=128, RADIUS=0.2

#define NB    8
#define NPER  4096
#define NS    1024
#define KNBR  64
#define CIN   64
#define HDIM  128
#define CFEAT 67
#define NCTR  (NB*NS)   // 8192
#define CAP   1024
#define R2    0.04f

// scratch (no allocation allowed -> device globals)
__device__ int g_fps[NCTR];          // local index within cloud of each FPS center
__device__ int g_nbr[NCTR*KNBR];     // local neighbor indices (valid set), unordered
__device__ int g_cnt[NCTR];          // number of valid neighbors (1..64)

// plain (non-FMA) squared distance, matching XLA's square-then-reduce codegen
__device__ __forceinline__ float dist2(float ax,float ay,float az,float bx,float by,float bz){
    float dx = ax - bx, dy = ay - by, dz = az - bz;
    return __fadd_rn(__fadd_rn(__fmul_rn(dx,dx), __fmul_rn(dy,dy)), __fmul_rn(dz,dz));
}

// ---------------------------------------------------------------------------
// Kernel 1: farthest point sampling. One block per cloud, 1024 threads,
// each thread owns 4 points (register-resident positions + running min-dist).
// ---------------------------------------------------------------------------
__global__ void __launch_bounds__(1024,1) fps_kernel(const float* __restrict__ pos){
    int b = blockIdx.x;
    const float* p = pos + (size_t)b * NPER * 3;
    int t = threadIdx.x;

    float px[4], py[4], pz[4], md[4];
#pragma unroll
    for (int j = 0; j < 4; ++j){
        int i = t + j*1024;
        px[j] = p[i*3+0]; py[j] = p[i*3+1]; pz[j] = p[i*3+2];
        md[j] = 1e10f;
    }

    __shared__ float sval[32];
    __shared__ int   sidx[32];
    __shared__ float cur[3];
    if (t == 0){
        cur[0] = p[0]; cur[1] = p[1]; cur[2] = p[2];
        g_fps[b*NS] = 0;
    }
    __syncthreads();

    const unsigned FULL = 0xffffffffu;
    for (int s = 1; s < NS; ++s){
        float cx = cur[0], cy = cur[1], cz = cur[2];
        float bv = -1.0f; int bi = 0;
#pragma unroll
        for (int j = 0; j < 4; ++j){
            float d = dist2(px[j], py[j], pz[j], cx, cy, cz);
            md[j] = fminf(md[j], d);
            if (md[j] > bv){ bv = md[j]; bi = t + j*1024; }   // strict > keeps smaller index on tie
        }
        // warp reduce: max value, tie -> min index (lexicographic semilattice)
#pragma unroll
        for (int o = 16; o > 0; o >>= 1){
            float ov = __shfl_down_sync(FULL, bv, o);
            int   oi = __shfl_down_sync(FULL, bi, o);
            if (ov > bv || (ov == bv && oi < bi)){ bv = ov; bi = oi; }
        }
        int w = t >> 5;
        if ((t & 31) == 0){ sval[w] = bv; sidx[w] = bi; }
        __syncthreads();
        // every warp redundantly reduces the 32 partials -> all threads know the winner
        {
            int l = t & 31;
            float v = sval[l]; int i = sidx[l];
#pragma unroll
            for (int o = 16; o > 0; o >>= 1){
                float ov = __shfl_down_sync(FULL, v, o);
                int   oi = __shfl_down_sync(FULL, i, o);
                if (ov > v || (ov == v && oi < i)){ v = ov; i = oi; }
            }
            i = __shfl_sync(FULL, i, 0);
            int jj = i - t;
            if (jj >= 0 && jj < 4096 && (jj & 1023) == 0){   // unique owner thread
                int j = jj >> 10;
                cur[0] = px[j]; cur[1] = py[j]; cur[2] = pz[j];
            }
            if (t == 0) g_fps[b*NS + s] = i;
        }
        __syncthreads();
    }
}

// ---------------------------------------------------------------------------
// Kernel 2: neighbor selection. One block per center. Compact points with
// d2<=r^2 into a candidate list; if more than K, exact rank-select the K
// nearest (tie -> smaller index, matching lax.top_k). Also writes pos_out /
// batch_out sections of the output.
// ---------------------------------------------------------------------------
__global__ void __launch_bounds__(128,8) select_kernel(const float* __restrict__ pos,
                                                       float* __restrict__ out, int out_size){
    int ci = blockIdx.x;
    int b  = ci >> 10;
    const float* p = pos + (size_t)b * NPER * 3;
    int cidx = g_fps[ci];
    float cx = p[cidx*3+0], cy = p[cidx*3+1], cz = p[cidx*3+2];

    __shared__ int   cnt;
    __shared__ float cd[CAP];
    __shared__ int   cix[CAP];
    if (threadIdx.x == 0) cnt = 0;
    __syncthreads();

    for (int i = threadIdx.x; i < NPER; i += 128){
        float d = dist2(p[i*3+0], p[i*3+1], p[i*3+2], cx, cy, cz);
        if (d <= R2){
            int q = atomicAdd(&cnt, 1);
            if (q < CAP){ cd[q] = d; cix[q] = i; }
        }
    }
    __syncthreads();
    int m = min(cnt, CAP);

    if (m <= KNBR){
        for (int j = threadIdx.x; j < m; j += 128) g_nbr[ci*KNBR + j] = cix[j];
        if (threadIdx.x == 0) g_cnt[ci] = m;
    } else {
        for (int j = threadIdx.x; j < m; j += 128){
            float dj = cd[j]; int ij = cix[j];
            int r = 0;
            for (int u = 0; u < m; ++u){
                float du = cd[u];
                r += (du < dj) || (du == dj && cix[u] < ij);
            }
            if (r < KNBR) g_nbr[ci*KNBR + r] = ij;
        }
        if (threadIdx.x == 0) g_cnt[ci] = KNBR;
    }

    if (threadIdx.x == 0 && out_size >= NCTR*HDIM + NCTR*3 + NCTR){
        float* po = out + NCTR*HDIM;
        po[ci*3+0] = cx; po[ci*3+1] = cy; po[ci*3+2] = cz;
        out[NCTR*HDIM + NCTR*3 + ci] = (float)b;
    }
}

// ---------------------------------------------------------------------------
// Kernel 3: fused gather + MLP + max aggregation.
// Block = 256 threads = 8 warps = 8 centers; weights staged once in SMEM.
// Each warp handles one center; lane owns 4 output channels (float4 of W);
// neighbors processed in tiles of 16 (acc = 16x float4 in registers).
// ---------------------------------------------------------------------------
#define SMEM_FLOATS (CFEAT*HDIM + HDIM + HDIM*HDIM + HDIM + 8*16*68 + 8*16*HDIM)

__global__ void __launch_bounds__(256,1) mlp_kernel(
        const float* __restrict__ x,  const float* __restrict__ pos,
        const float* __restrict__ W1, const float* __restrict__ b1,
        const float* __restrict__ W2, const float* __restrict__ b2,
        float* __restrict__ out){
    extern __shared__ float sm[];
    float* W1s = sm;                          // 67*128
    float* b1s = W1s + CFEAT*HDIM;            // 128
    float* W2s = b1s + HDIM;                  // 128*128
    float* b2s = W2s + HDIM*HDIM;             // 128
    float* fs  = b2s + HDIM;                  // 8*16*68
    float* h1s = fs  + 8*16*68;               // 8*16*128

    int tid = threadIdx.x;
    for (int i = tid; i < CFEAT*HDIM; i += 256) W1s[i] = W1[i];
    for (int i = tid; i < HDIM*HDIM;  i += 256) W2s[i] = W2[i];
    if (tid < HDIM){ b1s[tid] = b1[tid]; b2s[tid] = b2[tid]; }
    __syncthreads();

    int w = tid >> 5, lane = tid & 31;
    int ci = blockIdx.x * 8 + w;
    int b  = ci >> 10;
    size_t base = (size_t)b * NPER;
    int cidx = g_fps[ci];
    float cx = pos[(base + cidx)*3 + 0];
    float cy = pos[(base + cidx)*3 + 1];
    float cz = pos[(base + cidx)*3 + 2];
    int M = g_cnt[ci];
    int c0 = lane * 4;

    float4 b1v = *(const float4*)&b1s[c0];
    float4 b2v = *(const float4*)&b2s[c0];
    float4 om = make_float4(-1e9f, -1e9f, -1e9f, -1e9f);

    float* fw = fs  + w * 16 * 68;
    float* hw = h1s + w * 16 * HDIM;
    const int* nb = g_nbr + ci * KNBR;

    int tiles = (M + 15) >> 4;
    for (int t = 0; t < tiles; ++t){
        int n0 = t * 16;
        // gather feature tile [16 x 67] (pad rows with zeros)
        for (int r = 0; r < 16; ++r){
            int n = n0 + r;
            if (n < M){
                int gl = nb[n];
                const float* xr = x   + (base + gl) * CIN;
                const float* pr = pos + (base + gl) * 3;
                fw[r*68 + lane]      = xr[lane];
                fw[r*68 + lane + 32] = xr[lane + 32];
                if (lane < 3){
                    float c = (lane == 0) ? cx : (lane == 1) ? cy : cz;
                    fw[r*68 + 64 + lane] = pr[lane] - c;
                }
            } else {
                fw[r*68 + lane]      = 0.f;
                fw[r*68 + lane + 32] = 0.f;
                if (lane < 4) fw[r*68 + 64 + lane] = 0.f;
            }
        }
        __syncwarp();

        // GEMM1: [16x67] @ [67x128] -> h1 tile (relu)
        float4 acc[16];
#pragma unroll
        for (int r = 0; r < 16; ++r) acc[r] = b1v;
#pragma unroll 2
        for (int k = 0; k < CFEAT; ++k){
            float4 wv = *(const float4*)&W1s[k*HDIM + c0];
#pragma unroll
            for (int r = 0; r < 16; ++r){
                float f = fw[r*68 + k];
                acc[r].x = fmaf(f, wv.x, acc[r].x);
                acc[r].y = fmaf(f, wv.y, acc[r].y);
                acc[r].z = fmaf(f, wv.z, acc[r].z);
                acc[r].w = fmaf(f, wv.w, acc[r].w);
            }
        }
#pragma unroll
        for (int r = 0; r < 16; ++r){
            float4 h;
            h.x = fmaxf(acc[r].x, 0.f); h.y = fmaxf(acc[r].y, 0.f);
            h.z = fmaxf(acc[r].z, 0.f); h.w = fmaxf(acc[r].w, 0.f);
            *(float4*)&hw[r*HDIM + c0] = h;
        }
        __syncwarp();

        // GEMM2: [16x128] @ [128x128], fused relu + running max
#pragma unroll
        for (int r = 0; r < 16; ++r) acc[r] = b2v;
#pragma unroll 2
        for (int k = 0; k < HDIM; ++k){
            float4 wv = *(const float4*)&W2s[k*HDIM + c0];
#pragma unroll
            for (int r = 0; r < 16; ++r){
                float f = hw[r*HDIM + k];
                acc[r].x = fmaf(f, wv.x, acc[r].x);
                acc[r].y = fmaf(f, wv.y, acc[r].y);
                acc[r].z = fmaf(f, wv.z, acc[r].z);
                acc[r].w = fmaf(f, wv.w, acc[r].w);
            }
        }
        int nT = min(16, M - n0);
#pragma unroll
        for (int r = 0; r < 16; ++r){
            if (r < nT){
                om.x = fmaxf(om.x, fmaxf(acc[r].x, 0.f));
                om.y = fmaxf(om.y, fmaxf(acc[r].y, 0.f));
                om.z = fmaxf(om.z, fmaxf(acc[r].z, 0.f));
                om.w = fmaxf(om.w, fmaxf(acc[r].w, 0.f));
            }
        }
        __syncwarp();
    }

    *(float4*)&out[(size_t)ci*HDIM + c0] = om;
}

// ---------------------------------------------------------------------------
extern "C" void kernel_launch(void* const* d_in, const int* in_sizes, int n_in,
                              void* d_out, int out_size){
    // identify inputs by element count (robust to ordering); b1/b2 by order
    const float *x = 0, *pos = 0, *W1 = 0, *b1 = 0, *W2 = 0, *b2 = 0;
    for (int i = 0; i < n_in; ++i){
        int s = in_sizes[i];
        const float* p = (const float*)d_in[i];
        if      (s == NB*NPER*CIN) x   = p;
        else if (s == NB*NPER*3)   pos = p;
        else if (s == CFEAT*HDIM)  W1  = p;
        else if (s == HDIM*HDIM)   W2  = p;
        else if (s == HDIM){ if (!b1) b1 = p; else b2 = p; }
        // batch (32768 int32) is uniform -> unused
    }
    float* out = (float*)d_out;

    size_t smem = SMEM_FLOATS * sizeof(float);
    cudaFuncSetAttribute(mlp_kernel, cudaFuncAttributeMaxDynamicSharedMemorySize, (int)smem);

    fps_kernel<<<NB, 1024>>>(pos);
    select_kernel<<<NCTR, 128>>>(pos, out, out_size);
    mlp_kernel<<<NCTR/8, 256, smem>>>(x, pos, W1, b1, W2, b2, out);
}

// round 7
// speedup vs baseline: 2.8292x; 2.8292x over previous
#include <cuda_runtime.h>
#include <cstdint>

// PointNet++ SA layer: FPS -> radius ball query -> tf32 mma.sync MLP -> in-register max agg
#define NB    8
#define NPER  4096
#define NS    1024
#define KNBR  64
#define CIN   64
#define HDIM  128
#define NCTR  (NB*NS)      // 8192
#define NTILES (NCTR/2)    // 4096 tiles of 128 rows (2 centers x 64 slots)
#define CAP   1024
#define R2    0.04f

// SMEM strides (floats). Chosen for conflict-free mma fragment LDS.
#define S1 76    // A1 / W1T row stride (K=72 padded)
#define S2 132   // A2 / W2T row stride (K=128 padded)
#define W1T_OFF 0
#define W2T_OFF (128*S1)
#define A1_OFF  (W2T_OFF + 128*S2)
#define A2_OFF  (A1_OFF + 128*S1)
#define SMEM_FLOATS (A2_OFF + 128*S2)   // 53248 floats = 212992 B

// ---------------- device scratch ----------------
__device__ int g_fps[NCTR];
__device__ int g_nbr[NCTR*KNBR];
__device__ int g_cnt[NCTR];
__device__ int g_tile_ctr;

// ---------------- helpers ----------------
__device__ __forceinline__ float dist2(float ax,float ay,float az,float bx,float by,float bz){
    float dx = ax - bx, dy = ay - by, dz = az - bz;
    return __fadd_rn(__fadd_rn(__fmul_rn(dx,dx), __fmul_rn(dy,dy)), __fmul_rn(dz,dz));
}
__device__ __forceinline__ float rna_tf32(float f){
    float o; asm("cvt.rna.tf32.f32 %0, %1;" : "=f"(o) : "f"(f)); return o;
}

#define MMA_TF32(d, a, b) \
    asm volatile("mma.sync.aligned.m16n8k8.row.col.f32.tf32.tf32.f32 " \
        "{%0,%1,%2,%3}, {%4,%5,%6,%7}, {%8,%9}, {%0,%1,%2,%3};" \
        : "+f"((d)[0]), "+f"((d)[1]), "+f"((d)[2]), "+f"((d)[3]) \
        : "r"((a)[0]), "r"((a)[1]), "r"((a)[2]), "r"((a)[3]), \
          "r"((b)[0]), "r"((b)[1]))

// ---------------------------------------------------------------------------
// Kernel 1: FPS. One block per cloud, 1024 threads, 4 points/thread in regs.
// Per-step winner via packed u64 (dist_bits<<32 | ~idx) + shared atomicMax
// into a per-step slot -> exactly one __syncthreads per step.
// ---------------------------------------------------------------------------
__global__ void __launch_bounds__(1024,1) fps_kernel(const float* __restrict__ pos){
    int b = blockIdx.x, t = threadIdx.x;
    if (b == 0 && t == 0) g_tile_ctr = 0;          // reset ticket for this replay
    const float* p = pos + (size_t)b * NPER * 3;

    __shared__ unsigned long long slot[NS];
    for (int i = t; i < NS; i += 1024) slot[i] = 0ull;

    float px[4], py[4], pz[4], md[4];
#pragma unroll
    for (int j = 0; j < 4; ++j){
        int i = t + j*1024;
        px[j] = p[i*3+0]; py[j] = p[i*3+1]; pz[j] = p[i*3+2];
        md[j] = 1e10f;
    }
    float cx = p[0], cy = p[1], cz = p[2];
    if (t == 0) g_fps[b*NS] = 0;
    __syncthreads();

    const unsigned FULL = 0xffffffffu;
    for (int s = 1; s < NS; ++s){
        float bv = -1.0f; int bi = 0;
#pragma unroll
        for (int j = 0; j < 4; ++j){
            float d = dist2(px[j], py[j], pz[j], cx, cy, cz);
            md[j] = fminf(md[j], d);
            if (md[j] > bv){ bv = md[j]; bi = t + j*1024; }   // strict > : min index on tie
        }
        unsigned long long pk =
            ((unsigned long long)__float_as_uint(bv) << 32) | (unsigned)(0xFFFFFFFFu - bi);
#pragma unroll
        for (int o = 16; o > 0; o >>= 1){
            unsigned long long q = __shfl_down_sync(FULL, pk, o);
            pk = (q > pk) ? q : pk;
        }
        if ((t & 31) == 0) atomicMax(&slot[s], pk);
        __syncthreads();
        unsigned idx = 0xFFFFFFFFu - (unsigned)slot[s];
        if (t == 0) g_fps[b*NS + s] = (int)idx;
        cx = p[idx*3+0]; cy = p[idx*3+1]; cz = p[idx*3+2];   // L1 broadcast hit
    }
}

// ---------------------------------------------------------------------------
// Kernel 2: radius ball query (K nearest within r, exact top-k tie-break)
// + writes pos_out / batch_out sections.
// ---------------------------------------------------------------------------
__global__ void __launch_bounds__(128,8) select_kernel(const float* __restrict__ pos,
                                                       float* __restrict__ out, int out_size){
    int ci = blockIdx.x;
    int b  = ci >> 10;
    const float* p = pos + (size_t)b * NPER * 3;
    int cidx = g_fps[ci];
    float cx = p[cidx*3+0], cy = p[cidx*3+1], cz = p[cidx*3+2];

    __shared__ int   cnt;
    __shared__ float cd[CAP];
    __shared__ int   cix[CAP];
    if (threadIdx.x == 0) cnt = 0;
    __syncthreads();

    for (int i = threadIdx.x; i < NPER; i += 128){
        float d = dist2(p[i*3+0], p[i*3+1], p[i*3+2], cx, cy, cz);
        if (d <= R2){
            int q = atomicAdd(&cnt, 1);
            if (q < CAP){ cd[q] = d; cix[q] = i; }
        }
    }
    __syncthreads();
    int m = min(cnt, CAP);

    if (m <= KNBR){
        for (int j = threadIdx.x; j < m; j += 128) g_nbr[ci*KNBR + j] = cix[j];
        if (threadIdx.x == 0) g_cnt[ci] = m;
    } else {
        for (int j = threadIdx.x; j < m; j += 128){
            float dj = cd[j]; int ij = cix[j];
            int r = 0;
            for (int u = 0; u < m; ++u){
                float du = cd[u];
                r += (du < dj) || (du == dj && cix[u] < ij);
            }
            if (r < KNBR) g_nbr[ci*KNBR + r] = ij;
        }
        if (threadIdx.x == 0) g_cnt[ci] = KNBR;
    }

    if (threadIdx.x == 0 && out_size >= NCTR*HDIM + NCTR*3 + NCTR){
        float* po = out + NCTR*HDIM;
        po[ci*3+0] = cx; po[ci*3+1] = cy; po[ci*3+2] = cz;
        out[NCTR*HDIM + NCTR*3 + ci] = (float)b;
    }
}

// ---------------------------------------------------------------------------
// Warp-tile GEMM: 64x32 per warp via 4x4 grid of m16n8k8 tf32 mma.sync.
// A row-major [128 x SA], B = W^T row(n)-major [128 x SB] (col-major operand).
// ---------------------------------------------------------------------------
template<int KSTEPS, int SA, int SB>
__device__ __forceinline__ void gemm_tile(const float* __restrict__ As,
                                          const float* __restrict__ Bs,
                                          int warpR, int warpC, int g, int tg,
                                          float acc[4][4][4]){
    const uint32_t* Au = (const uint32_t*)As;
    const uint32_t* Bu = (const uint32_t*)Bs;
#pragma unroll 1
    for (int ks = 0; ks < KSTEPS; ++ks){
        int k0 = ks*8 + tg;
        uint32_t a[4][4], bf[4][2];
#pragma unroll
        for (int mt = 0; mt < 4; ++mt){
            const uint32_t* ar = Au + (warpR + mt*16 + g)*SA + k0;
            a[mt][0] = ar[0];
            a[mt][1] = ar[8*SA];
            a[mt][2] = ar[4];
            a[mt][3] = ar[8*SA + 4];
        }
#pragma unroll
        for (int nt = 0; nt < 4; ++nt){
            const uint32_t* br = Bu + (warpC + nt*8 + g)*SB + k0;
            bf[nt][0] = br[0];
            bf[nt][1] = br[4];
        }
#pragma unroll
        for (int mt = 0; mt < 4; ++mt)
#pragma unroll
            for (int nt = 0; nt < 4; ++nt)
                MMA_TF32(acc[mt][nt], a[mt], bf[nt]);
    }
}

// ---------------------------------------------------------------------------
// Kernel 3: persistent tf32 MLP. Tile = 128 rows (2 centers) x 128 cols.
// ---------------------------------------------------------------------------
__global__ void __launch_bounds__(256,1) mlp_kernel(
        const float* __restrict__ x,  const float* __restrict__ pos,
        const float* __restrict__ W1, const float* __restrict__ b1,
        const float* __restrict__ W2, const float* __restrict__ b2,
        float* __restrict__ out){
    extern __shared__ float sm[];
    float* W1s = sm + W1T_OFF;
    float* W2s = sm + W2T_OFF;
    float* A1s = sm + A1_OFF;
    float* A2s = sm + A2_OFF;

    int tid = threadIdx.x, w = tid >> 5, lane = tid & 31;
    int g = lane >> 2, tg = lane & 3;
    int warpR = (w >> 2) * 64;     // which center's rows
    int warpC = (w & 3) * 32;      // output column block

    // one-time: transpose + tf32-round weights into SMEM
    for (int i = tid; i < 67*HDIM; i += 256){
        int k = i >> 7, n = i & 127;
        W1s[n*S1 + k] = rna_tf32(W1[i]);
    }
    for (int i = tid; i < 128*5; i += 256){         // zero pad k=67..71
        int n = i / 5, k = 67 + i % 5;
        W1s[n*S1 + k] = 0.f;
    }
    for (int i = tid; i < HDIM*HDIM; i += 256){
        int k = i >> 7, n = i & 127;
        W2s[n*S2 + k] = rna_tf32(W2[i]);
    }
    float b1v[8], b2v[8];
#pragma unroll
    for (int nt = 0; nt < 4; ++nt){
        int c = warpC + nt*8 + 2*tg;
        b1v[nt*2] = b1[c]; b1v[nt*2+1] = b1[c+1];
        b2v[nt*2] = b2[c]; b2v[nt*2+1] = b2[c+1];
    }

    const unsigned FULL = 0xffffffffu;
    __shared__ int s_tile;
    for (;;){
        if (tid == 0) s_tile = atomicAdd(&g_tile_ctr, 1);
        __syncthreads();
        int tile = s_tile;
        if (tile >= NTILES) break;
        int c0 = tile*2;
        int M0 = g_cnt[c0], M1 = g_cnt[c0+1];

        // ---- gather A1 [128 x 72] (tf32-rounded, zero-padded) ----
        {
            int r = tid >> 1, q = tid & 1;
            int ci = c0 + (r >> 6); int sl = r & 63;
            int M = (r >> 6) ? M1 : M0;
            bool v = sl < M;
            float* arow = A1s + r*S1;
            size_t base = (size_t)(ci >> 10) * NPER;
            const float4* xr = nullptr;
            int gl = 0;
            if (v){
                gl = g_nbr[ci*KNBR + sl];
                xr = (const float4*)(x + (base + gl)*CIN);
            }
#pragma unroll
            for (int j = 0; j < 8; ++j){
                int col = q*8 + j;
                float4 t = v ? xr[col] : make_float4(0,0,0,0);
                t.x = rna_tf32(t.x); t.y = rna_tf32(t.y);
                t.z = rna_tf32(t.z); t.w = rna_tf32(t.w);
                *(float4*)(arow + col*4) = t;
            }
            if (q == 0){
                float4 t = make_float4(0,0,0,0);
                if (v){
                    const float* pr = pos + (base + gl)*3;
                    const float* pc = pos + (base + g_fps[ci])*3;
                    t.x = rna_tf32(pr[0] - pc[0]);
                    t.y = rna_tf32(pr[1] - pc[1]);
                    t.z = rna_tf32(pr[2] - pc[2]);
                }
                *(float4*)(arow + 64) = t;
            } else {
                *(float4*)(arow + 68) = make_float4(0,0,0,0);
            }
        }
        __syncthreads();

        // ---- GEMM1: [128x72] @ W1T -> h1, relu+round -> A2 ----
        float acc[4][4][4];
#pragma unroll
        for (int mt = 0; mt < 4; ++mt)
#pragma unroll
            for (int nt = 0; nt < 4; ++nt)
#pragma unroll
                for (int i = 0; i < 4; ++i) acc[mt][nt][i] = 0.f;
        gemm_tile<9, S1, S1>(A1s, W1s, warpR, warpC, g, tg, acc);

#pragma unroll
        for (int mt = 0; mt < 4; ++mt){
            int r0 = warpR + mt*16 + g;
#pragma unroll
            for (int nt = 0; nt < 4; ++nt){
                int cc = warpC + nt*8 + 2*tg;
                float* d = acc[mt][nt];
                float2 h0, h1;
                h0.x = rna_tf32(fmaxf(d[0] + b1v[nt*2],   0.f));
                h0.y = rna_tf32(fmaxf(d[1] + b1v[nt*2+1], 0.f));
                h1.x = rna_tf32(fmaxf(d[2] + b1v[nt*2],   0.f));
                h1.y = rna_tf32(fmaxf(d[3] + b1v[nt*2+1], 0.f));
                *(float2*)&A2s[r0*S2 + cc]     = h0;
                *(float2*)&A2s[(r0+8)*S2 + cc] = h1;
            }
        }
        __syncthreads();

        // ---- GEMM2: [128x128] @ W2T, fused relu + masked max ----
#pragma unroll
        for (int mt = 0; mt < 4; ++mt)
#pragma unroll
            for (int nt = 0; nt < 4; ++nt)
#pragma unroll
                for (int i = 0; i < 4; ++i) acc[mt][nt][i] = 0.f;
        gemm_tile<16, S2, S2>(A2s, W2s, warpR, warpC, g, tg, acc);

        int M = (w >> 2) ? M1 : M0;
        float cm[8];
#pragma unroll
        for (int i = 0; i < 8; ++i) cm[i] = -1e9f;
#pragma unroll
        for (int mt = 0; mt < 4; ++mt){
            int rr0 = mt*16 + g;
            bool v0 = rr0 < M, v1 = (rr0 + 8) < M;
#pragma unroll
            for (int nt = 0; nt < 4; ++nt){
                float* d = acc[mt][nt];
                if (v0){
                    cm[nt*2]   = fmaxf(cm[nt*2],   fmaxf(d[0] + b2v[nt*2],   0.f));
                    cm[nt*2+1] = fmaxf(cm[nt*2+1], fmaxf(d[1] + b2v[nt*2+1], 0.f));
                }
                if (v1){
                    cm[nt*2]   = fmaxf(cm[nt*2],   fmaxf(d[2] + b2v[nt*2],   0.f));
                    cm[nt*2+1] = fmaxf(cm[nt*2+1], fmaxf(d[3] + b2v[nt*2+1], 0.f));
                }
            }
        }
#pragma unroll
        for (int o = 16; o >= 4; o >>= 1)
#pragma unroll
            for (int i = 0; i < 8; ++i)
                cm[i] = fmaxf(cm[i], __shfl_down_sync(FULL, cm[i], o));

        if (lane < 4){
            int ciout = c0 + (w >> 2);
#pragma unroll
            for (int nt = 0; nt < 4; ++nt){
                int c = warpC + nt*8 + 2*lane;
                float2 o2; o2.x = cm[nt*2]; o2.y = cm[nt*2+1];
                *(float2*)&out[(size_t)ciout*HDIM + c] = o2;
            }
        }
    }
}

// ---------------------------------------------------------------------------
extern "C" void kernel_launch(void* const* d_in, const int* in_sizes, int n_in,
                              void* d_out, int out_size){
    const float *x = 0, *pos = 0, *W1 = 0, *b1 = 0, *W2 = 0, *b2 = 0;
    for (int i = 0; i < n_in; ++i){
        int s = in_sizes[i];
        const float* p = (const float*)d_in[i];
        if      (s == NB*NPER*CIN)  x   = p;
        else if (s == NB*NPER*3)    pos = p;
        else if (s == 67*HDIM)      W1  = p;
        else if (s == HDIM*HDIM)    W2  = p;
        else if (s == HDIM){ if (!b1) b1 = p; else b2 = p; }
    }
    float* out = (float*)d_out;

    size_t smem = SMEM_FLOATS * sizeof(float);
    cudaFuncSetAttribute(mlp_kernel, cudaFuncAttributeMaxDynamicSharedMemorySize, (int)smem);

    fps_kernel<<<NB, 1024>>>(pos);
    select_kernel<<<NCTR, 128>>>(pos, out, out_size);
    mlp_kernel<<<148, 256, smem>>>(x, pos, W1, b1, W2, b2, out);
}

// round 8
// speedup vs baseline: 3.8988x; 1.3781x over previous
#include <cuda_runtime.h>
#include <cstdint>

// PointNet++ SA layer: FPS -> radius ball query -> tf32 mma.sync MLP -> in-register max agg
#define NB    8
#define NPER  4096
#define NS    1024
#define KNBR  64
#define CIN   64
#define HDIM  128
#define NCTR  (NB*NS)      // 8192
#define NTILES (NCTR/2)    // 4096 tiles of 128 rows (2 centers x 64 slots)
#define CAP   1024
#define R2    0.04f

// SMEM strides (floats). Chosen for conflict-free mma fragment LDS.
#define S1 76    // A1 / W1T row stride (K=72 padded)
#define S2 132   // A2 / W2T row stride (K=128 padded)
#define W1T_OFF 0
#define W2T_OFF (128*S1)
#define A1_OFF  (W2T_OFF + 128*S2)
#define A2_OFF  (A1_OFF + 128*S1)
#define SMEM_FLOATS (A2_OFF + 128*S2)   // 53248 floats = 212992 B

// ---------------- device scratch ----------------
__device__ int g_fps[NCTR];
__device__ int g_nbr[NCTR*KNBR];
__device__ int g_cnt[NCTR];
__device__ int g_tile_ctr;

// ---------------- helpers ----------------
__device__ __forceinline__ float dist2(float ax,float ay,float az,float bx,float by,float bz){
    float dx = ax - bx, dy = ay - by, dz = az - bz;
    return __fadd_rn(__fadd_rn(__fmul_rn(dx,dx), __fmul_rn(dy,dy)), __fmul_rn(dz,dz));
}
__device__ __forceinline__ float rna_tf32(float f){
    float o; asm("cvt.rna.tf32.f32 %0, %1;" : "=f"(o) : "f"(f)); return o;
}

#define MMA_TF32(d, a, b) \
    asm volatile("mma.sync.aligned.m16n8k8.row.col.f32.tf32.tf32.f32 " \
        "{%0,%1,%2,%3}, {%4,%5,%6,%7}, {%8,%9}, {%0,%1,%2,%3};" \
        : "+f"((d)[0]), "+f"((d)[1]), "+f"((d)[2]), "+f"((d)[3]) \
        : "r"((a)[0]), "r"((a)[1]), "r"((a)[2]), "r"((a)[3]), \
          "r"((b)[0]), "r"((b)[1]))

// ---------------------------------------------------------------------------
// Kernel 1: FPS. One block per cloud, 1024 threads, 4 points/thread in regs.
// Per-step winner: HW REDUX (value bits max, then min index among matches),
// cross-warp via parity double-buffered 32-entry shared array.
// Exactly ONE __syncthreads per step; no atomics; no u64 shfl chains.
// ---------------------------------------------------------------------------
__global__ void __launch_bounds__(1024,1) fps_kernel(const float* __restrict__ pos){
    int b = blockIdx.x, t = threadIdx.x;
    if (b == 0 && t == 0) g_tile_ctr = 0;          // reset ticket for this replay
    const float* p = pos + (size_t)b * NPER * 3;

    __shared__ unsigned sv[2][32];   // per-warp winner value bits, parity buffered
    __shared__ unsigned si[2][32];   // per-warp winner global index

    float px[4], py[4], pz[4], md[4];
#pragma unroll
    for (int j = 0; j < 4; ++j){
        int i = t + j*1024;
        px[j] = p[i*3+0]; py[j] = p[i*3+1]; pz[j] = p[i*3+2];
        md[j] = 1e10f;
    }
    float cx = p[0], cy = p[1], cz = p[2];
    if (t == 0) g_fps[b*NS] = 0;
    __syncthreads();

    const unsigned FULL = 0xffffffffu;
    int w = t >> 5, lane = t & 31;

    for (int s = 1; s < NS; ++s){
        // update running min-dist; thread-local max (positive floats)
        float tv = -1.0f;
#pragma unroll
        for (int j = 0; j < 4; ++j){
            float d = dist2(px[j], py[j], pz[j], cx, cy, cz);
            md[j] = fminf(md[j], d);
            tv = fmaxf(tv, md[j]);
        }
        // warp stage: max value bits, then min index among matches
        unsigned wv = __reduce_max_sync(FULL, __float_as_uint(tv));
        unsigned mi = 0xFFFFFFFFu;
#pragma unroll
        for (int j = 0; j < 4; ++j){
            unsigned gi = (unsigned)(t + j*1024);
            if (__float_as_uint(md[j]) == wv) mi = min(mi, gi);
        }
        unsigned wi = __reduce_min_sync(FULL, mi);

        int par = s & 1;
        if (lane == 0){ sv[par][w] = wv; si[par][w] = wi; }
        __syncthreads();

        // cross-warp stage: 32 entries, one per lane
        unsigned lv = sv[par][lane], li = si[par][lane];
        unsigned gv = __reduce_max_sync(FULL, lv);
        unsigned cand = (lv == gv) ? li : 0xFFFFFFFFu;
        unsigned gidx = __reduce_min_sync(FULL, cand);

        if (t == 0) g_fps[b*NS + s] = (int)gidx;
        cx = p[gidx*3+0]; cy = p[gidx*3+1]; cz = p[gidx*3+2];   // L1 broadcast hit
    }
}

// ---------------------------------------------------------------------------
// Kernel 2: radius ball query (K nearest within r, exact top-k tie-break)
// + writes pos_out / batch_out sections.
// ---------------------------------------------------------------------------
__global__ void __launch_bounds__(128,8) select_kernel(const float* __restrict__ pos,
                                                       float* __restrict__ out, int out_size){
    int ci = blockIdx.x;
    int b  = ci >> 10;
    const float* p = pos + (size_t)b * NPER * 3;
    int cidx = g_fps[ci];
    float cx = p[cidx*3+0], cy = p[cidx*3+1], cz = p[cidx*3+2];

    __shared__ int   cnt;
    __shared__ float cd[CAP];
    __shared__ int   cix[CAP];
    if (threadIdx.x == 0) cnt = 0;
    __syncthreads();

    for (int i = threadIdx.x; i < NPER; i += 128){
        float d = dist2(p[i*3+0], p[i*3+1], p[i*3+2], cx, cy, cz);
        if (d <= R2){
            int q = atomicAdd(&cnt, 1);
            if (q < CAP){ cd[q] = d; cix[q] = i; }
        }
    }
    __syncthreads();
    int m = min(cnt, CAP);

    if (m <= KNBR){
        for (int j = threadIdx.x; j < m; j += 128) g_nbr[ci*KNBR + j] = cix[j];
        if (threadIdx.x == 0) g_cnt[ci] = m;
    } else {
        for (int j = threadIdx.x; j < m; j += 128){
            float dj = cd[j]; int ij = cix[j];
            int r = 0;
            for (int u = 0; u < m; ++u){
                float du = cd[u];
                r += (du < dj) || (du == dj && cix[u] < ij);
            }
            if (r < KNBR) g_nbr[ci*KNBR + r] = ij;
        }
        if (threadIdx.x == 0) g_cnt[ci] = KNBR;
    }

    if (threadIdx.x == 0 && out_size >= NCTR*HDIM + NCTR*3 + NCTR){
        float* po = out + NCTR*HDIM;
        po[ci*3+0] = cx; po[ci*3+1] = cy; po[ci*3+2] = cz;
        out[NCTR*HDIM + NCTR*3 + ci] = (float)b;
    }
}

// ---------------------------------------------------------------------------
// Warp-tile GEMM: 64x32 per warp via 4x4 grid of m16n8k8 tf32 mma.sync.
// A row-major [128 x SA], B = W^T row(n)-major [128 x SB] (col-major operand).
// ---------------------------------------------------------------------------
template<int KSTEPS, int SA, int SB>
__device__ __forceinline__ void gemm_tile(const float* __restrict__ As,
                                          const float* __restrict__ Bs,
                                          int warpR, int warpC, int g, int tg,
                                          float acc[4][4][4]){
    const uint32_t* Au = (const uint32_t*)As;
    const uint32_t* Bu = (const uint32_t*)Bs;
#pragma unroll 1
    for (int ks = 0; ks < KSTEPS; ++ks){
        int k0 = ks*8 + tg;
        uint32_t a[4][4], bf[4][2];
#pragma unroll
        for (int mt = 0; mt < 4; ++mt){
            const uint32_t* ar = Au + (warpR + mt*16 + g)*SA + k0;
            a[mt][0] = ar[0];
            a[mt][1] = ar[8*SA];
            a[mt][2] = ar[4];
            a[mt][3] = ar[8*SA + 4];
        }
#pragma unroll
        for (int nt = 0; nt < 4; ++nt){
            const uint32_t* br = Bu + (warpC + nt*8 + g)*SB + k0;
            bf[nt][0] = br[0];
            bf[nt][1] = br[4];
        }
#pragma unroll
        for (int mt = 0; mt < 4; ++mt)
#pragma unroll
            for (int nt = 0; nt < 4; ++nt)
                MMA_TF32(acc[mt][nt], a[mt], bf[nt]);
    }
}

// ---------------------------------------------------------------------------
// Kernel 3: persistent tf32 MLP. Tile = 128 rows (2 centers) x 128 cols.
// ---------------------------------------------------------------------------
__global__ void __launch_bounds__(256,1) mlp_kernel(
        const float* __restrict__ x,  const float* __restrict__ pos,
        const float* __restrict__ W1, const float* __restrict__ b1,
        const float* __restrict__ W2, const float* __restrict__ b2,
        float* __restrict__ out){
    extern __shared__ float sm[];
    float* W1s = sm + W1T_OFF;
    float* W2s = sm + W2T_OFF;
    float* A1s = sm + A1_OFF;
    float* A2s = sm + A2_OFF;

    int tid = threadIdx.x, w = tid >> 5, lane = tid & 31;
    int g = lane >> 2, tg = lane & 3;
    int warpR = (w >> 2) * 64;     // which center's rows
    int warpC = (w & 3) * 32;      // output column block

    // one-time: transpose + tf32-round weights into SMEM
    for (int i = tid; i < 67*HDIM; i += 256){
        int k = i >> 7, n = i & 127;
        W1s[n*S1 + k] = rna_tf32(W1[i]);
    }
    for (int i = tid; i < 128*5; i += 256){         // zero pad k=67..71
        int n = i / 5, k = 67 + i % 5;
        W1s[n*S1 + k] = 0.f;
    }
    for (int i = tid; i < HDIM*HDIM; i += 256){
        int k = i >> 7, n = i & 127;
        W2s[n*S2 + k] = rna_tf32(W2[i]);
    }
    float b1v[8], b2v[8];
#pragma unroll
    for (int nt = 0; nt < 4; ++nt){
        int c = warpC + nt*8 + 2*tg;
        b1v[nt*2] = b1[c]; b1v[nt*2+1] = b1[c+1];
        b2v[nt*2] = b2[c]; b2v[nt*2+1] = b2[c+1];
    }

    const unsigned FULL = 0xffffffffu;
    __shared__ int s_tile;
    for (;;){
        if (tid == 0) s_tile = atomicAdd(&g_tile_ctr, 1);
        __syncthreads();
        int tile = s_tile;
        if (tile >= NTILES) break;
        int c0 = tile*2;
        int M0 = g_cnt[c0], M1 = g_cnt[c0+1];

        // ---- gather A1 [128 x 72] (tf32-rounded, zero-padded) ----
        {
            int r = tid >> 1, q = tid & 1;
            int ci = c0 + (r >> 6); int sl = r & 63;
            int M = (r >> 6) ? M1 : M0;
            bool v = sl < M;
            float* arow = A1s + r*S1;
            size_t base = (size_t)(ci >> 10) * NPER;
            const float4* xr = nullptr;
            int gl = 0;
            if (v){
                gl = g_nbr[ci*KNBR + sl];
                xr = (const float4*)(x + (base + gl)*CIN);
            }
#pragma unroll
            for (int j = 0; j < 8; ++j){
                int col = q*8 + j;
                float4 t = v ? xr[col] : make_float4(0,0,0,0);
                t.x = rna_tf32(t.x); t.y = rna_tf32(t.y);
                t.z = rna_tf32(t.z); t.w = rna_tf32(t.w);
                *(float4*)(arow + col*4) = t;
            }
            if (q == 0){
                float4 t = make_float4(0,0,0,0);
                if (v){
                    const float* pr = pos + (base + gl)*3;
                    const float* pc = pos + (base + g_fps[ci])*3;
                    t.x = rna_tf32(pr[0] - pc[0]);
                    t.y = rna_tf32(pr[1] - pc[1]);
                    t.z = rna_tf32(pr[2] - pc[2]);
                }
                *(float4*)(arow + 64) = t;
            } else {
                *(float4*)(arow + 68) = make_float4(0,0,0,0);
            }
        }
        __syncthreads();

        // ---- GEMM1: [128x72] @ W1T -> h1, relu+round -> A2 ----
        float acc[4][4][4];
#pragma unroll
        for (int mt = 0; mt < 4; ++mt)
#pragma unroll
            for (int nt = 0; nt < 4; ++nt)
#pragma unroll
                for (int i = 0; i < 4; ++i) acc[mt][nt][i] = 0.f;
        gemm_tile<9, S1, S1>(A1s, W1s, warpR, warpC, g, tg, acc);

#pragma unroll
        for (int mt = 0; mt < 4; ++mt){
            int r0 = warpR + mt*16 + g;
#pragma unroll
            for (int nt = 0; nt < 4; ++nt){
                int cc = warpC + nt*8 + 2*tg;
                float* d = acc[mt][nt];
                float2 h0, h1;
                h0.x = rna_tf32(fmaxf(d[0] + b1v[nt*2],   0.f));
                h0.y = rna_tf32(fmaxf(d[1] + b1v[nt*2+1], 0.f));
                h1.x = rna_tf32(fmaxf(d[2] + b1v[nt*2],   0.f));
                h1.y = rna_tf32(fmaxf(d[3] + b1v[nt*2+1], 0.f));
                *(float2*)&A2s[r0*S2 + cc]     = h0;
                *(float2*)&A2s[(r0+8)*S2 + cc] = h1;
            }
        }
        __syncthreads();

        // ---- GEMM2: [128x128] @ W2T, fused relu + masked max ----
#pragma unroll
        for (int mt = 0; mt < 4; ++mt)
#pragma unroll
            for (int nt = 0; nt < 4; ++nt)
#pragma unroll
                for (int i = 0; i < 4; ++i) acc[mt][nt][i] = 0.f;
        gemm_tile<16, S2, S2>(A2s, W2s, warpR, warpC, g, tg, acc);

        int M = (w >> 2) ? M1 : M0;
        float cm[8];
#pragma unroll
        for (int i = 0; i < 8; ++i) cm[i] = -1e9f;
#pragma unroll
        for (int mt = 0; mt < 4; ++mt){
            int rr0 = mt*16 + g;
            bool v0 = rr0 < M, v1 = (rr0 + 8) < M;
#pragma unroll
            for (int nt = 0; nt < 4; ++nt){
                float* d = acc[mt][nt];
                if (v0){
                    cm[nt*2]   = fmaxf(cm[nt*2],   fmaxf(d[0] + b2v[nt*2],   0.f));
                    cm[nt*2+1] = fmaxf(cm[nt*2+1], fmaxf(d[1] + b2v[nt*2+1], 0.f));
                }
                if (v1){
                    cm[nt*2]   = fmaxf(cm[nt*2],   fmaxf(d[2] + b2v[nt*2],   0.f));
                    cm[nt*2+1] = fmaxf(cm[nt*2+1], fmaxf(d[3] + b2v[nt*2+1], 0.f));
                }
            }
        }
#pragma unroll
        for (int o = 16; o >= 4; o >>= 1)
#pragma unroll
            for (int i = 0; i < 8; ++i)
                cm[i] = fmaxf(cm[i], __shfl_down_sync(FULL, cm[i], o));

        if (lane < 4){
            int ciout = c0 + (w >> 2);
#pragma unroll
            for (int nt = 0; nt < 4; ++nt){
                int c = warpC + nt*8 + 2*lane;
                float2 o2; o2.x = cm[nt*2]; o2.y = cm[nt*2+1];
                *(float2*)&out[(size_t)ciout*HDIM + c] = o2;
            }
        }
    }
}

// ---------------------------------------------------------------------------
extern "C" void kernel_launch(void* const* d_in, const int* in_sizes, int n_in,
                              void* d_out, int out_size){
    const float *x = 0, *pos = 0, *W1 = 0, *b1 = 0, *W2 = 0, *b2 = 0;
    for (int i = 0; i < n_in; ++i){
        int s = in_sizes[i];
        const float* p = (const float*)d_in[i];
        if      (s == NB*NPER*CIN)  x   = p;
        else if (s == NB*NPER*3)    pos = p;
        else if (s == 67*HDIM)      W1  = p;
        else if (s == HDIM*HDIM)    W2  = p;
        else if (s == HDIM){ if (!b1) b1 = p; else b2 = p; }
    }
    float* out = (float*)d_out;

    size_t smem = SMEM_FLOATS * sizeof(float);
    cudaFuncSetAttribute(mlp_kernel, cudaFuncAttributeMaxDynamicSharedMemorySize, (int)smem);

    fps_kernel<<<NB, 1024>>>(pos);
    select_kernel<<<NCTR, 128>>>(pos, out, out_size);
    mlp_kernel<<<148, 256, smem>>>(x, pos, W1, b1, W2, b2, out);
}

// round 11
// speedup vs baseline: 4.2253x; 1.0837x over previous
#include <cuda_runtime.h>
#include <cstdint>

// PointNet++ SA layer, fused producer/consumer:
//   blocks 0-7: FPS (streaming center production, release-published)
//   all blocks: persistent consumers (ball query + tf32 mma.sync MLP + max agg)
#define NB    8
#define NPER  4096
#define NS    1024
#define KNBR  64
#define CIN   64
#define HDIM  128
#define NCTR  (NB*NS)      // 8192
#define NTILES (NCTR/2)    // 4096 tiles of 128 rows (2 centers x 64 slots)
#define CAP   1024
#define R2    0.04f

// SMEM strides (floats). Chosen for conflict-free mma fragment LDS.
#define S1 76    // A1 / W1T row stride (K=72 padded)
#define S2 132   // A2 / W2T row stride (K=128 padded)
#define W1T_OFF 0
#define W2T_OFF (128*S1)
#define A1_OFF  (W2T_OFF + 128*S2)
#define A2_OFF  (A1_OFF + 128*S1)
#define SMEM_FLOATS (A2_OFF + 128*S2)   // 53248 floats = 212992 B

// ---------------- device scratch ----------------
__device__ int g_fps[NCTR];
__device__ int g_prog[NB];      // per-cloud produced-center count
__device__ int g_tile_ctr;

// ---------------- helpers ----------------
__device__ __forceinline__ float dist2(float ax,float ay,float az,float bx,float by,float bz){
    float dx = ax - bx, dy = ay - by, dz = az - bz;
    return __fadd_rn(__fadd_rn(__fmul_rn(dx,dx), __fmul_rn(dy,dy)), __fmul_rn(dz,dz));
}
__device__ __forceinline__ float rna_tf32(float f){
    float o; asm("cvt.rna.tf32.f32 %0, %1;" : "=f"(o) : "f"(f)); return o;
}
__device__ __forceinline__ void st_rel(int* a, int v){
    asm volatile("st.release.gpu.global.s32 [%0], %1;" :: "l"(a), "r"(v) : "memory");
}
__device__ __forceinline__ int ld_acq(const int* a){
    int v; asm volatile("ld.acquire.gpu.global.s32 %0, [%1];" : "=r"(v) : "l"(a) : "memory");
    return v;
}

#define MMA_TF32(d, a, b) \
    asm volatile("mma.sync.aligned.m16n8k8.row.col.f32.tf32.tf32.f32 " \
        "{%0,%1,%2,%3}, {%4,%5,%6,%7}, {%8,%9}, {%0,%1,%2,%3};" \
        : "+f"((d)[0]), "+f"((d)[1]), "+f"((d)[2]), "+f"((d)[3]) \
        : "r"((a)[0]), "r"((a)[1]), "r"((a)[2]), "r"((a)[3]), \
          "r"((b)[0]), "r"((b)[1]))

// ---------------------------------------------------------------------------
__global__ void init_kernel(){
    if (threadIdx.x == 0) g_tile_ctr = 0;
    if (threadIdx.x < NB) g_prog[threadIdx.x] = 0;
}

// ---------------------------------------------------------------------------
// Warp-tile GEMM: 64x32 per warp via 4x4 grid of m16n8k8 tf32 mma.sync.
// ---------------------------------------------------------------------------
template<int KSTEPS, int SA, int SB>
__device__ __forceinline__ void gemm_tile(const float* __restrict__ As,
                                          const float* __restrict__ Bs,
                                          int warpR, int warpC, int g, int tg,
                                          float acc[4][4][4]){
    const uint32_t* Au = (const uint32_t*)As;
    const uint32_t* Bu = (const uint32_t*)Bs;
#pragma unroll 1
    for (int ks = 0; ks < KSTEPS; ++ks){
        int k0 = ks*8 + tg;
        uint32_t a[4][4], bf[4][2];
#pragma unroll
        for (int mt = 0; mt < 4; ++mt){
            const uint32_t* ar = Au + (warpR + mt*16 + g)*SA + k0;
            a[mt][0] = ar[0];
            a[mt][1] = ar[8*SA];
            a[mt][2] = ar[4];
            a[mt][3] = ar[8*SA + 4];
        }
#pragma unroll
        for (int nt = 0; nt < 4; ++nt){
            const uint32_t* br = Bu + (warpC + nt*8 + g)*SB + k0;
            bf[nt][0] = br[0];
            bf[nt][1] = br[4];
        }
#pragma unroll
        for (int mt = 0; mt < 4; ++mt)
#pragma unroll
            for (int nt = 0; nt < 4; ++nt)
                MMA_TF32(acc[mt][nt], a[mt], bf[nt]);
    }
}

// ---------------------------------------------------------------------------
// Fused kernel: 148 blocks x 256 threads, all co-resident (1 block/SM).
// ---------------------------------------------------------------------------
__global__ void __launch_bounds__(256,1) fused_kernel(
        const float* __restrict__ x,  const float* __restrict__ pos,
        const float* __restrict__ W1, const float* __restrict__ b1,
        const float* __restrict__ W2, const float* __restrict__ b2,
        float* __restrict__ out, int out_size){
    extern __shared__ float sm[];
    float* W1s = sm + W1T_OFF;
    float* W2s = sm + W2T_OFF;
    float* A1s = sm + A1_OFF;
    float* A2s = sm + A2_OFF;

    __shared__ unsigned sv[2][8], si[2][8];   // FPS cross-warp stage
    __shared__ int s_tile;
    __shared__ int s_cnt[2], s_M[2], s_nb[2][KNBR];

    int tid = threadIdx.x, w = tid >> 5, lane = tid & 31;
    const unsigned FULL = 0xffffffffu;

    // ======================= producer: FPS (blocks 0-7) =======================
    if (blockIdx.x < NB){
        int b = blockIdx.x;
        const float* p = pos + (size_t)b * NPER * 3;

        float px[16], py[16], pz[16], md[16];
#pragma unroll
        for (int j = 0; j < 16; ++j){
            int i = tid + j*256;
            px[j] = p[i*3+0]; py[j] = p[i*3+1]; pz[j] = p[i*3+2];
            md[j] = 1e10f;
        }
        float cx = p[0], cy = p[1], cz = p[2];
        if (tid == 0){
            g_fps[b*NS] = 0;
            st_rel(&g_prog[b], 1);
        }
        __syncthreads();

        for (int s = 1; s < NS; ++s){
            float bv = -1.0f; unsigned bi = 0;
#pragma unroll
            for (int j = 0; j < 16; ++j){
                float d = dist2(px[j], py[j], pz[j], cx, cy, cz);
                md[j] = fminf(md[j], d);
                if (md[j] > bv){ bv = md[j]; bi = (unsigned)(tid + j*256); } // strict >: min index
            }
            unsigned wv = __reduce_max_sync(FULL, __float_as_uint(bv));
            unsigned mi = (__float_as_uint(bv) == wv) ? bi : 0xFFFFFFFFu;
            unsigned wi = __reduce_min_sync(FULL, mi);

            int par = s & 1;
            if (lane == 0){ sv[par][w] = wv; si[par][w] = wi; }
            __syncthreads();

            unsigned lv = (lane < 8) ? sv[par][lane] : 0u;
            unsigned gv = __reduce_max_sync(FULL, lv);
            unsigned cand = (lane < 8 && lv == gv) ? si[par][lane] : 0xFFFFFFFFu;
            unsigned gidx = __reduce_min_sync(FULL, cand);

            if (tid == 0){
                g_fps[b*NS + s] = (int)gidx;
                st_rel(&g_prog[b], s + 1);
            }
            cx = p[gidx*3+0]; cy = p[gidx*3+1]; cz = p[gidx*3+2];
        }
        __syncthreads();
    }

    // ======================= consumer: all blocks =======================
    // stage weights (transpose + tf32-round)
    for (int i = tid; i < 67*HDIM; i += 256){
        int k = i >> 7, n = i & 127;
        W1s[n*S1 + k] = rna_tf32(W1[i]);
    }
    for (int i = tid; i < 128*5; i += 256){          // zero pad k=67..71
        int n = i / 5, k = 67 + i % 5;
        W1s[n*S1 + k] = 0.f;
    }
    for (int i = tid; i < HDIM*HDIM; i += 256){
        int k = i >> 7, n = i & 127;
        W2s[n*S2 + k] = rna_tf32(W2[i]);
    }
    int g = lane >> 2, tg = lane & 3;
    int warpR = (w >> 2) * 64;
    int warpC = (w & 3) * 32;
    float b1v[8], b2v[8];
#pragma unroll
    for (int nt = 0; nt < 4; ++nt){
        int c = warpC + nt*8 + 2*tg;
        b1v[nt*2] = b1[c]; b1v[nt*2+1] = b1[c+1];
        b2v[nt*2] = b2[c]; b2v[nt*2+1] = b2[c+1];
    }
    __syncthreads();

    for (;;){
        if (tid == 0) s_tile = atomicAdd(&g_tile_ctr, 1);
        __syncthreads();
        int ticket = s_tile;
        if (ticket >= NTILES) break;
        int cloud = ticket & 7, pair = ticket >> 3;
        int c0 = cloud*NS + pair*2;

        // wait until both centers of this tile exist
        if (tid == 0){
            int need = pair*2 + 2, bo = 32;
            while (ld_acq(&g_prog[cloud]) < need){
                __nanosleep(bo);
                if (bo < 1024) bo <<= 1;
            }
        }
        __syncthreads();

        const float* p = pos + (size_t)cloud * NPER * 3;
        size_t base = (size_t)cloud * NPER;

        // ---- inlined select: 2 groups of 128 threads, one center each ----
        int grp = tid >> 7, lt = tid & 127;
        int ci = c0 + grp;
        int cidx = g_fps[ci];
        float cx = p[cidx*3+0], cy = p[cidx*3+1], cz = p[cidx*3+2];
        float* cdg = A2s + grp*CAP;
        int*   cig = ((int*)A2s) + 2*CAP + grp*CAP;
        if (lt == 0) s_cnt[grp] = 0;
        __syncthreads();

        for (int i = lt; i < NPER; i += 128){
            float d = dist2(p[i*3+0], p[i*3+1], p[i*3+2], cx, cy, cz);
            if (d <= R2){
                int q = atomicAdd(&s_cnt[grp], 1);
                if (q < CAP){ cdg[q] = d; cig[q] = i; }
            }
        }
        __syncthreads();
        int m = min(s_cnt[grp], CAP);
        if (m <= KNBR){
            for (int j = lt; j < m; j += 128) s_nb[grp][j] = cig[j];
            if (lt == 0) s_M[grp] = m;
        } else {
            for (int j = lt; j < m; j += 128){
                float dj = cdg[j]; int ij = cig[j];
                int r = 0;
                for (int u = 0; u < m; ++u){
                    float du = cdg[u];
                    r += (du < dj) || (du == dj && cig[u] < ij);
                }
                if (r < KNBR) s_nb[grp][r] = ij;
            }
            if (lt == 0) s_M[grp] = KNBR;
        }
        if (lt == 0 && out_size >= NCTR*HDIM + NCTR*3 + NCTR){
            float* po = out + NCTR*HDIM;
            po[ci*3+0] = cx; po[ci*3+1] = cy; po[ci*3+2] = cz;
            out[NCTR*HDIM + NCTR*3 + ci] = (float)cloud;
        }
        __syncthreads();
        int M0 = s_M[0], M1 = s_M[1];

        // ---- gather A1 [128 x 72] (tf32-rounded, zero-padded) ----
        {
            int r = tid >> 1, q = tid & 1;
            int rg = r >> 6; int sl = r & 63;
            int M = rg ? M1 : M0;
            bool v = sl < M;
            float* arow = A1s + r*S1;
            const float4* xr = nullptr;
            int gl = 0;
            if (v){
                gl = s_nb[rg][sl];
                xr = (const float4*)(x + (base + gl)*CIN);
            }
#pragma unroll
            for (int j = 0; j < 8; ++j){
                int col = q*8 + j;
                float4 t = v ? xr[col] : make_float4(0,0,0,0);
                t.x = rna_tf32(t.x); t.y = rna_tf32(t.y);
                t.z = rna_tf32(t.z); t.w = rna_tf32(t.w);
                *(float4*)(arow + col*4) = t;
            }
            if (q == 0){
                float4 t = make_float4(0,0,0,0);
                if (v){
                    const float* pr = p + gl*3;
                    const float* pc = p + g_fps[c0 + rg]*3;
                    t.x = rna_tf32(pr[0] - pc[0]);
                    t.y = rna_tf32(pr[1] - pc[1]);
                    t.z = rna_tf32(pr[2] - pc[2]);
                }
                *(float4*)(arow + 64) = t;
            } else {
                *(float4*)(arow + 68) = make_float4(0,0,0,0);
            }
        }
        __syncthreads();

        // ---- GEMM1: [128x72] @ W1T -> relu+round -> A2 ----
        float acc[4][4][4];
#pragma unroll
        for (int mt = 0; mt < 4; ++mt)
#pragma unroll
            for (int nt = 0; nt < 4; ++nt)
#pragma unroll
                for (int i = 0; i < 4; ++i) acc[mt][nt][i] = 0.f;
        gemm_tile<9, S1, S1>(A1s, W1s, warpR, warpC, g, tg, acc);

#pragma unroll
        for (int mt = 0; mt < 4; ++mt){
            int r0 = warpR + mt*16 + g;
#pragma unroll
            for (int nt = 0; nt < 4; ++nt){
                int cc = warpC + nt*8 + 2*tg;
                float* d = acc[mt][nt];
                float2 h0, h1;
                h0.x = rna_tf32(fmaxf(d[0] + b1v[nt*2],   0.f));
                h0.y = rna_tf32(fmaxf(d[1] + b1v[nt*2+1], 0.f));
                h1.x = rna_tf32(fmaxf(d[2] + b1v[nt*2],   0.f));
                h1.y = rna_tf32(fmaxf(d[3] + b1v[nt*2+1], 0.f));
                *(float2*)&A2s[r0*S2 + cc]     = h0;
                *(float2*)&A2s[(r0+8)*S2 + cc] = h1;
            }
        }
        __syncthreads();

        // ---- GEMM2: [128x128] @ W2T, fused relu + masked max ----
#pragma unroll
        for (int mt = 0; mt < 4; ++mt)
#pragma unroll
            for (int nt = 0; nt < 4; ++nt)
#pragma unroll
                for (int i = 0; i < 4; ++i) acc[mt][nt][i] = 0.f;
        gemm_tile<16, S2, S2>(A2s, W2s, warpR, warpC, g, tg, acc);

        int M = (w >> 2) ? M1 : M0;
        float cm[8];
#pragma unroll
        for (int i = 0; i < 8; ++i) cm[i] = -1e9f;
#pragma unroll
        for (int mt = 0; mt < 4; ++mt){
            int rr0 = mt*16 + g;
            bool v0 = rr0 < M, v1 = (rr0 + 8) < M;
#pragma unroll
            for (int nt = 0; nt < 4; ++nt){
                float* d = acc[mt][nt];
                if (v0){
                    cm[nt*2]   = fmaxf(cm[nt*2],   fmaxf(d[0] + b2v[nt*2],   0.f));
                    cm[nt*2+1] = fmaxf(cm[nt*2+1], fmaxf(d[1] + b2v[nt*2+1], 0.f));
                }
                if (v1){
                    cm[nt*2]   = fmaxf(cm[nt*2],   fmaxf(d[2] + b2v[nt*2],   0.f));
                    cm[nt*2+1] = fmaxf(cm[nt*2+1], fmaxf(d[3] + b2v[nt*2+1], 0.f));
                }
            }
        }
#pragma unroll
        for (int o = 16; o >= 4; o >>= 1)
#pragma unroll
            for (int i = 0; i < 8; ++i)
                cm[i] = fmaxf(cm[i], __shfl_down_sync(FULL, cm[i], o));

        if (lane < 4){
            int ciout = c0 + (w >> 2);
#pragma unroll
            for (int nt = 0; nt < 4; ++nt){
                int c = warpC + nt*8 + 2*lane;
                float2 o2; o2.x = cm[nt*2]; o2.y = cm[nt*2+1];
                *(float2*)&out[(size_t)ciout*HDIM + c] = o2;
            }
        }
    }
}

// ---------------------------------------------------------------------------
extern "C" void kernel_launch(void* const* d_in, const int* in_sizes, int n_in,
                              void* d_out, int out_size){
    const float *x = 0, *pos = 0, *W1 = 0, *b1 = 0, *W2 = 0, *b2 = 0;
    for (int i = 0; i < n_in; ++i){
        int s = in_sizes[i];
        const float* p = (const float*)d_in[i];
        if      (s == NB*NPER*CIN)  x   = p;
        else if (s == NB*NPER*3)    pos = p;
        else if (s == 67*HDIM)      W1  = p;
        else if (s == HDIM*HDIM)    W2  = p;
        else if (s == HDIM){ if (!b1) b1 = p; else b2 = p; }
    }
    float* out = (float*)d_out;

    size_t smem = SMEM_FLOATS * sizeof(float);
    cudaFuncSetAttribute(fused_kernel, cudaFuncAttributeMaxDynamicSharedMemorySize, (int)smem);

    init_kernel<<<1, 32>>>();
    fused_kernel<<<148, 256, smem>>>(x, pos, W1, b1, W2, b2, out, out_size);
}

// round 12
// speedup vs baseline: 4.8278x; 1.1426x over previous
#include <cuda_runtime.h>
#include <cstdint>

// PointNet++ SA layer, fused producer/consumer, 1024-thread blocks:
//   blocks 0-7: FPS (1024 thr, 4 pts/thr) streaming centers, release-published
//   all blocks: persistent consumers (ball query + tf32 mma.sync MLP + max agg)
#define NB    8
#define NPER  4096
#define NS    1024
#define KNBR  64
#define CIN   64
#define HDIM  128
#define NCTR  (NB*NPER/4)  // 8192
#define NTILES (NCTR/2)    // 4096 tiles of 128 rows (2 centers x 64 slots)
#define CAP   1024
#define R2    0.04f

// SMEM strides (floats). Chosen for conflict-free mma fragment LDS.
#define S1 76    // A1 / W1T row stride (K=72 padded)
#define S2 132   // A2 / W2T row stride (K=128 padded)
#define W1T_OFF 0
#define W2T_OFF (128*S1)
#define A1_OFF  (W2T_OFF + 128*S2)
#define A2_OFF  (A1_OFF + 128*S1)
#define SMEM_FLOATS (A2_OFF + 128*S2)   // 53248 floats = 212992 B

// ---------------- device scratch ----------------
__device__ int g_fps[NCTR];
__device__ int g_prog[NB];      // per-cloud produced-center count
__device__ int g_tile_ctr;

// ---------------- helpers ----------------
__device__ __forceinline__ float dist2(float ax,float ay,float az,float bx,float by,float bz){
    float dx = ax - bx, dy = ay - by, dz = az - bz;
    return __fadd_rn(__fadd_rn(__fmul_rn(dx,dx), __fmul_rn(dy,dy)), __fmul_rn(dz,dz));
}
__device__ __forceinline__ float rna_tf32(float f){
    float o; asm("cvt.rna.tf32.f32 %0, %1;" : "=f"(o) : "f"(f)); return o;
}
__device__ __forceinline__ void st_rel(int* a, int v){
    asm volatile("st.release.gpu.global.s32 [%0], %1;" :: "l"(a), "r"(v) : "memory");
}
__device__ __forceinline__ int ld_acq(const int* a){
    int v; asm volatile("ld.acquire.gpu.global.s32 %0, [%1];" : "=r"(v) : "l"(a) : "memory");
    return v;
}

#define MMA_TF32(d, a, b) \
    asm volatile("mma.sync.aligned.m16n8k8.row.col.f32.tf32.tf32.f32 " \
        "{%0,%1,%2,%3}, {%4,%5,%6,%7}, {%8,%9}, {%0,%1,%2,%3};" \
        : "+f"((d)[0]), "+f"((d)[1]), "+f"((d)[2]), "+f"((d)[3]) \
        : "r"((a)[0]), "r"((a)[1]), "r"((a)[2]), "r"((a)[3]), \
          "r"((b)[0]), "r"((b)[1]))

// ---------------------------------------------------------------------------
__global__ void init_kernel(){
    if (threadIdx.x == 0) g_tile_ctr = 0;
    if (threadIdx.x < NB) g_prog[threadIdx.x] = 0;
}

// ---------------------------------------------------------------------------
// Per-warp GEMM: 16 rows x 32 cols via 1x4 grid of m16n8k8 tf32 mma.sync.
// ---------------------------------------------------------------------------
template<int KSTEPS, int SA, int SB>
__device__ __forceinline__ void gemm_tile16(const float* __restrict__ As,
                                            const float* __restrict__ Bs,
                                            int warpR, int warpC, int g, int tg,
                                            float acc[4][4]){
    const uint32_t* Au = (const uint32_t*)As;
    const uint32_t* Bu = (const uint32_t*)Bs;
#pragma unroll 1
    for (int ks = 0; ks < KSTEPS; ++ks){
        int k0 = ks*8 + tg;
        uint32_t a[4], bf[4][2];
        const uint32_t* ar = Au + (warpR + g)*SA + k0;
        a[0] = ar[0];
        a[1] = ar[8*SA];
        a[2] = ar[4];
        a[3] = ar[8*SA + 4];
#pragma unroll
        for (int nt = 0; nt < 4; ++nt){
            const uint32_t* br = Bu + (warpC + nt*8 + g)*SB + k0;
            bf[nt][0] = br[0];
            bf[nt][1] = br[4];
        }
#pragma unroll
        for (int nt = 0; nt < 4; ++nt)
            MMA_TF32(acc[nt], a, bf[nt]);
    }
}

// ---------------------------------------------------------------------------
// Fused kernel: 148 blocks x 1024 threads, all co-resident (1 block/SM).
// ---------------------------------------------------------------------------
__global__ void __launch_bounds__(1024,1) fused_kernel(
        const float* __restrict__ x,  const float* __restrict__ pos,
        const float* __restrict__ W1, const float* __restrict__ b1,
        const float* __restrict__ W2, const float* __restrict__ b2,
        float* __restrict__ out, int out_size){
    extern __shared__ float sm[];
    float* W1s = sm + W1T_OFF;
    float* W2s = sm + W2T_OFF;
    float* A1s = sm + A1_OFF;
    float* A2s = sm + A2_OFF;

    __shared__ unsigned sv[2][32], si[2][32];    // FPS cross-warp stage
    __shared__ int s_tile;
    __shared__ int s_cnt[2], s_M[2], s_nb[2][KNBR];
    __shared__ unsigned aggU[256];               // column-max agg (float bits, >=0)
    __shared__ float bbs[256];                   // b1 | b2

    int tid = threadIdx.x, w = tid >> 5, lane = tid & 31;
    const unsigned FULL = 0xffffffffu;

    // ======================= producer: FPS (blocks 0-7) =======================
    if (blockIdx.x < NB){
        int b = blockIdx.x;
        const float* p = pos + (size_t)b * NPER * 3;

        float px[4], py[4], pz[4], md[4];
#pragma unroll
        for (int j = 0; j < 4; ++j){
            int i = tid + j*1024;
            px[j] = p[i*3+0]; py[j] = p[i*3+1]; pz[j] = p[i*3+2];
            md[j] = 1e10f;
        }
        float cx = p[0], cy = p[1], cz = p[2];
        if (tid == 0) g_fps[b*NS] = 0;
        __syncthreads();

        for (int s = 1; s < NS; ++s){
            float tv = -1.0f;
#pragma unroll
            for (int j = 0; j < 4; ++j){
                float d = dist2(px[j], py[j], pz[j], cx, cy, cz);
                md[j] = fminf(md[j], d);
                tv = fmaxf(tv, md[j]);
            }
            unsigned wv = __reduce_max_sync(FULL, __float_as_uint(tv));
            unsigned mi = 0xFFFFFFFFu;
#pragma unroll
            for (int j = 0; j < 4; ++j){
                unsigned gi = (unsigned)(tid + j*1024);
                if (__float_as_uint(md[j]) == wv) mi = min(mi, gi);
            }
            unsigned wi = __reduce_min_sync(FULL, mi);

            int par = s & 1;
            if (lane == 0){ sv[par][w] = wv; si[par][w] = wi; }
            __syncthreads();

            unsigned lv = sv[par][lane];
            unsigned gv = __reduce_max_sync(FULL, lv);
            unsigned cand = (lv == gv) ? si[par][lane] : 0xFFFFFFFFu;
            unsigned gidx = __reduce_min_sync(FULL, cand);

            if (tid == 0){
                g_fps[b*NS + s] = (int)gidx;
                if ((s & 3) == 3) st_rel(&g_prog[b], s + 1);   // publish every 4
            }
            cx = p[gidx*3+0]; cy = p[gidx*3+1]; cz = p[gidx*3+2];
        }
        __syncthreads();
    }

    // ======================= consumer: all blocks =======================
    // stage weights (transpose + tf32-round) + biases
    for (int i = tid; i < 67*HDIM; i += 1024){
        int k = i >> 7, n = i & 127;
        W1s[n*S1 + k] = rna_tf32(W1[i]);
    }
    for (int i = tid; i < 128*5; i += 1024){          // zero pad k=67..71
        int n = i / 5, k = 67 + i % 5;
        W1s[n*S1 + k] = 0.f;
    }
    for (int i = tid; i < HDIM*HDIM; i += 1024){
        int k = i >> 7, n = i & 127;
        W2s[n*S2 + k] = rna_tf32(W2[i]);
    }
    if (tid < 128){ bbs[tid] = b1[tid]; bbs[128 + tid] = b2[tid]; }
    if (tid < 256) aggU[tid] = 0u;

    int g = lane >> 2, tg = lane & 3;
    int warpR = (w >> 2) * 16;     // 8 row-groups of 16 rows
    int warpC = (w & 3) * 32;      // 4 column blocks
    int center = warpR >> 6;       // 0 or 1
    __syncthreads();

    for (;;){
        if (tid == 0) s_tile = atomicAdd(&g_tile_ctr, 1);
        __syncthreads();
        int ticket = s_tile;
        if (ticket >= NTILES) break;
        int cloud = ticket & 7, pair = ticket >> 3;
        int c0 = cloud*NS + pair*2;

        // wait until both centers of this tile exist
        if (tid == 0){
            int need = pair*2 + 2, bo = 32;
            while (ld_acq(&g_prog[cloud]) < need){
                __nanosleep(bo);
                if (bo < 1024) bo <<= 1;
            }
        }
        __syncthreads();

        const float* p = pos + (size_t)cloud * NPER * 3;
        size_t base = (size_t)cloud * NPER;

        // ---- inlined select: 2 groups of 512 threads, one center each ----
        int grp = tid >> 9, lt = tid & 511;
        int ci = c0 + grp;
        int cidx = g_fps[ci];
        float cx = p[cidx*3+0], cy = p[cidx*3+1], cz = p[cidx*3+2];
        float* cdg = A2s + grp*CAP;
        int*   cig = ((int*)A2s) + 2*CAP + grp*CAP;
        if (lt == 0) s_cnt[grp] = 0;
        __syncthreads();

        for (int i = lt; i < NPER; i += 512){
            float d = dist2(p[i*3+0], p[i*3+1], p[i*3+2], cx, cy, cz);
            if (d <= R2){
                int q = atomicAdd(&s_cnt[grp], 1);
                if (q < CAP){ cdg[q] = d; cig[q] = i; }
            }
        }
        __syncthreads();
        int m = min(s_cnt[grp], CAP);
        if (m <= KNBR){
            for (int j = lt; j < m; j += 512) s_nb[grp][j] = cig[j];
            if (lt == 0) s_M[grp] = m;
        } else {
            for (int j = lt; j < m; j += 512){
                float dj = cdg[j]; int ij = cig[j];
                int r = 0;
                for (int u = 0; u < m; ++u){
                    float du = cdg[u];
                    r += (du < dj) || (du == dj && cig[u] < ij);
                }
                if (r < KNBR) s_nb[grp][r] = ij;
            }
            if (lt == 0) s_M[grp] = KNBR;
        }
        if (lt == 0 && out_size >= NCTR*HDIM + NCTR*3 + NCTR){
            float* po = out + NCTR*HDIM;
            po[ci*3+0] = cx; po[ci*3+1] = cy; po[ci*3+2] = cz;
            out[NCTR*HDIM + NCTR*3 + ci] = (float)cloud;
        }
        __syncthreads();
        int M0 = s_M[0], M1 = s_M[1];

        // ---- gather A1 [128 x 72] (tf32-rounded, zero-padded); 8 thr/row ----
        {
            int r = tid >> 3, q = tid & 7;
            int rg = r >> 6; int sl = r & 63;
            int M = rg ? M1 : M0;
            bool v = sl < M;
            float* arow = A1s + r*S1;
            const float4* xr = nullptr;
            int gl = 0;
            if (v){
                gl = s_nb[rg][sl];
                xr = (const float4*)(x + (base + gl)*CIN);
            }
            float4 t = v ? xr[q] : make_float4(0,0,0,0);
            t.x = rna_tf32(t.x); t.y = rna_tf32(t.y);
            t.z = rna_tf32(t.z); t.w = rna_tf32(t.w);
            *(float4*)(arow + 4*q) = t;
            t = v ? xr[q+8] : make_float4(0,0,0,0);
            t.x = rna_tf32(t.x); t.y = rna_tf32(t.y);
            t.z = rna_tf32(t.z); t.w = rna_tf32(t.w);
            *(float4*)(arow + 4*q + 32) = t;
            if (q == 0){
                float4 d4 = make_float4(0,0,0,0);
                if (v){
                    const float* pr = p + gl*3;
                    const float* pc = p + g_fps[c0 + rg]*3;
                    d4.x = rna_tf32(pr[0] - pc[0]);
                    d4.y = rna_tf32(pr[1] - pc[1]);
                    d4.z = rna_tf32(pr[2] - pc[2]);
                }
                *(float4*)(arow + 64) = d4;
            } else if (q == 1){
                *(float4*)(arow + 68) = make_float4(0,0,0,0);
            }
        }
        __syncthreads();

        // ---- GEMM1: [128x72] @ W1T -> relu+round -> A2 ----
        float acc[4][4];
#pragma unroll
        for (int nt = 0; nt < 4; ++nt)
#pragma unroll
            for (int i = 0; i < 4; ++i) acc[nt][i] = 0.f;
        gemm_tile16<9, S1, S1>(A1s, W1s, warpR, warpC, g, tg, acc);

        {
            int r0 = warpR + g;
#pragma unroll
            for (int nt = 0; nt < 4; ++nt){
                int cc = warpC + nt*8 + 2*tg;
                float ba = bbs[cc], bb = bbs[cc+1];
                float* d = acc[nt];
                float2 h0, h1;
                h0.x = rna_tf32(fmaxf(d[0] + ba, 0.f));
                h0.y = rna_tf32(fmaxf(d[1] + bb, 0.f));
                h1.x = rna_tf32(fmaxf(d[2] + ba, 0.f));
                h1.y = rna_tf32(fmaxf(d[3] + bb, 0.f));
                *(float2*)&A2s[r0*S2 + cc]     = h0;
                *(float2*)&A2s[(r0+8)*S2 + cc] = h1;
            }
        }
        __syncthreads();

        // ---- GEMM2: [128x128] @ W2T, fused relu + masked max ----
#pragma unroll
        for (int nt = 0; nt < 4; ++nt)
#pragma unroll
            for (int i = 0; i < 4; ++i) acc[nt][i] = 0.f;
        gemm_tile16<16, S2, S2>(A2s, W2s, warpR, warpC, g, tg, acc);

        {
            int M = center ? M1 : M0;
            int rIn = (warpR & 63) + g;
            bool v0 = rIn < M, v1 = (rIn + 8) < M;
            float cm[8];
#pragma unroll
            for (int i = 0; i < 8; ++i) cm[i] = 0.f;   // valid contributions are >= 0
#pragma unroll
            for (int nt = 0; nt < 4; ++nt){
                int cc = warpC + nt*8 + 2*tg;
                float ba = bbs[128+cc], bb = bbs[128+cc+1];
                float* d = acc[nt];
                if (v0){
                    cm[nt*2]   = fmaxf(cm[nt*2],   fmaxf(d[0] + ba, 0.f));
                    cm[nt*2+1] = fmaxf(cm[nt*2+1], fmaxf(d[1] + bb, 0.f));
                }
                if (v1){
                    cm[nt*2]   = fmaxf(cm[nt*2],   fmaxf(d[2] + ba, 0.f));
                    cm[nt*2+1] = fmaxf(cm[nt*2+1], fmaxf(d[3] + bb, 0.f));
                }
            }
#pragma unroll
            for (int o = 16; o >= 4; o >>= 1)
#pragma unroll
                for (int i = 0; i < 8; ++i)
                    cm[i] = fmaxf(cm[i], __shfl_down_sync(FULL, cm[i], o));
            if (lane < 4){       // g==0 lanes hold warp-level col maxima (tg=lane)
#pragma unroll
                for (int nt = 0; nt < 4; ++nt){
                    int cc = warpC + nt*8 + 2*lane;
                    atomicMax(&aggU[center*128 + cc],     __float_as_uint(cm[nt*2]));
                    atomicMax(&aggU[center*128 + cc + 1], __float_as_uint(cm[nt*2+1]));
                }
            }
        }
        __syncthreads();

        if (tid < 256){
            int cen = tid >> 7, col = tid & 127;
            out[(size_t)(c0 + cen)*HDIM + col] = __uint_as_float(aggU[tid]);
            aggU[tid] = 0u;      // reset for next ticket (same thread -> no race)
        }
    }
}

// ---------------------------------------------------------------------------
extern "C" void kernel_launch(void* const* d_in, const int* in_sizes, int n_in,
                              void* d_out, int out_size){
    const float *x = 0, *pos = 0, *W1 = 0, *b1 = 0, *W2 = 0, *b2 = 0;
    for (int i = 0; i < n_in; ++i){
        int s = in_sizes[i];
        const float* p = (const float*)d_in[i];
        if      (s == NB*NPER*CIN)  x   = p;
        else if (s == NB*NPER*3)    pos = p;
        else if (s == 67*HDIM)      W1  = p;
        else if (s == HDIM*HDIM)    W2  = p;
        else if (s == HDIM){ if (!b1) b1 = p; else b2 = p; }
    }
    float* out = (float*)d_out;

    size_t smem = SMEM_FLOATS * sizeof(float);
    cudaFuncSetAttribute(fused_kernel, cudaFuncAttributeMaxDynamicSharedMemorySize, (int)smem);

    init_kernel<<<1, 32>>>();
    fused_kernel<<<148, 1024, smem>>>(x, pos, W1, b1, W2, b2, out, out_size);
}

// round 13
// speedup vs baseline: 5.1197x; 1.0605x over previous
#include <cuda_runtime.h>
#include <cstdint>

// PointNet++ SA layer, fused producer/consumer, 1024-thread blocks:
//   blocks 0-7: FPS (1024 thr, 4 pts/thr, packed f32x2 math) streaming centers
//   all blocks: persistent consumers (ball query + tf32 mma.sync MLP + max agg)
#define NB    8
#define NPER  4096
#define NS    1024
#define KNBR  64
#define CIN   64
#define HDIM  128
#define NCTR  (NB*NPER/4)  // 8192
#define NTILES (NCTR/2)    // 4096 tiles of 128 rows (2 centers x 64 slots)
#define CAP   1024
#define R2    0.04f

// SMEM strides (floats). Chosen for conflict-free mma fragment LDS.
#define S1 76    // A1 / W1T row stride (K=72 padded)
#define S2 132   // A2 / W2T row stride (K=128 padded)
#define W1T_OFF 0
#define W2T_OFF (128*S1)
#define A1_OFF  (W2T_OFF + 128*S2)
#define A2_OFF  (A1_OFF + 128*S1)
#define SMEM_FLOATS (A2_OFF + 128*S2)   // 53248 floats = 212992 B

// ---------------- device scratch ----------------
__device__ int g_fps[NCTR];
__device__ int g_prog[NB];      // per-cloud produced-center count
__device__ int g_tile_ctr;

// ---------------- helpers ----------------
__device__ __forceinline__ float dist2(float ax,float ay,float az,float bx,float by,float bz){
    float dx = ax - bx, dy = ay - by, dz = az - bz;
    return __fadd_rn(__fadd_rn(__fmul_rn(dx,dx), __fmul_rn(dy,dy)), __fmul_rn(dz,dz));
}
__device__ __forceinline__ float rna_tf32(float f){
    float o; asm("cvt.rna.tf32.f32 %0, %1;" : "=f"(o) : "f"(f)); return o;
}
__device__ __forceinline__ void st_rel(int* a, int v){
    asm volatile("st.release.gpu.global.s32 [%0], %1;" :: "l"(a), "r"(v) : "memory");
}
__device__ __forceinline__ int ld_acq(const int* a){
    int v; asm volatile("ld.acquire.gpu.global.s32 %0, [%1];" : "=r"(v) : "l"(a) : "memory");
    return v;
}

// ---- packed f32x2 (Blackwell base ISA; per-lane IEEE rn => bit-exact) ----
__device__ __forceinline__ uint64_t pack2(float lo, float hi){
    uint64_t r; asm("mov.b64 %0, {%1,%2};" : "=l"(r) : "f"(lo), "f"(hi)); return r;
}
__device__ __forceinline__ void unpack2(uint64_t v, float& lo, float& hi){
    asm("mov.b64 {%0,%1}, %2;" : "=f"(lo), "=f"(hi) : "l"(v));
}
#define SUB2(o,a,b) asm("sub.rn.f32x2 %0, %1, %2;" : "=l"(o) : "l"(a), "l"(b))
#define MUL2(o,a,b) asm("mul.rn.f32x2 %0, %1, %2;" : "=l"(o) : "l"(a), "l"(b))
#define ADD2(o,a,b) asm("add.rn.f32x2 %0, %1, %2;" : "=l"(o) : "l"(a), "l"(b))

#define MMA_TF32(d, a, b) \
    asm volatile("mma.sync.aligned.m16n8k8.row.col.f32.tf32.tf32.f32 " \
        "{%0,%1,%2,%3}, {%4,%5,%6,%7}, {%8,%9}, {%0,%1,%2,%3};" \
        : "+f"((d)[0]), "+f"((d)[1]), "+f"((d)[2]), "+f"((d)[3]) \
        : "r"((a)[0]), "r"((a)[1]), "r"((a)[2]), "r"((a)[3]), \
          "r"((b)[0]), "r"((b)[1]))

// ---------------------------------------------------------------------------
__global__ void init_kernel(){
    if (threadIdx.x == 0) g_tile_ctr = 0;
    if (threadIdx.x < NB) g_prog[threadIdx.x] = 0;
}

// ---------------------------------------------------------------------------
// Per-warp GEMM: 16 rows x 32 cols via 1x4 grid of m16n8k8 tf32 mma.sync.
// ---------------------------------------------------------------------------
template<int KSTEPS, int SA, int SB>
__device__ __forceinline__ void gemm_tile16(const float* __restrict__ As,
                                            const float* __restrict__ Bs,
                                            int warpR, int warpC, int g, int tg,
                                            float acc[4][4]){
    const uint32_t* Au = (const uint32_t*)As;
    const uint32_t* Bu = (const uint32_t*)Bs;
#pragma unroll 1
    for (int ks = 0; ks < KSTEPS; ++ks){
        int k0 = ks*8 + tg;
        uint32_t a[4], bf[4][2];
        const uint32_t* ar = Au + (warpR + g)*SA + k0;
        a[0] = ar[0];
        a[1] = ar[8*SA];
        a[2] = ar[4];
        a[3] = ar[8*SA + 4];
#pragma unroll
        for (int nt = 0; nt < 4; ++nt){
            const uint32_t* br = Bu + (warpC + nt*8 + g)*SB + k0;
            bf[nt][0] = br[0];
            bf[nt][1] = br[4];
        }
#pragma unroll
        for (int nt = 0; nt < 4; ++nt)
            MMA_TF32(acc[nt], a, bf[nt]);
    }
}

// ---------------------------------------------------------------------------
// Fused kernel: 148 blocks x 1024 threads, all co-resident (1 block/SM).
// ---------------------------------------------------------------------------
__global__ void __launch_bounds__(1024,1) fused_kernel(
        const float* __restrict__ x,  const float* __restrict__ pos,
        const float* __restrict__ W1, const float* __restrict__ b1,
        const float* __restrict__ W2, const float* __restrict__ b2,
        float* __restrict__ out, int out_size){
    extern __shared__ float sm[];
    float* W1s = sm + W1T_OFF;
    float* W2s = sm + W2T_OFF;
    float* A1s = sm + A1_OFF;
    float* A2s = sm + A2_OFF;

    __shared__ unsigned sv[2][32], si[2][32];    // FPS cross-warp stage
    __shared__ int s_tile;
    __shared__ int s_cnt[2], s_M[2], s_nb[2][KNBR];
    __shared__ unsigned aggU[256];               // column-max agg (float bits, >=0)
    __shared__ float bbs[256];                   // b1 | b2

    int tid = threadIdx.x, w = tid >> 5, lane = tid & 31;
    const unsigned FULL = 0xffffffffu;

    // ======================= producer: FPS (blocks 0-7) =======================
    if (blockIdx.x < NB){
        int b = blockIdx.x;
        const float* p = pos + (size_t)b * NPER * 3;

        // 4 points/thread as 2 packed pairs: pair q holds points (tid+2q*1024, tid+(2q+1)*1024)
        uint64_t PX[2], PY[2], PZ[2];
        float md[4];
#pragma unroll
        for (int q = 0; q < 2; ++q){
            int i0 = tid + (2*q)*1024, i1 = tid + (2*q+1)*1024;
            PX[q] = pack2(p[i0*3+0], p[i1*3+0]);
            PY[q] = pack2(p[i0*3+1], p[i1*3+1]);
            PZ[q] = pack2(p[i0*3+2], p[i1*3+2]);
            md[2*q] = 1e10f; md[2*q+1] = 1e10f;
        }
        float cx = p[0], cy = p[1], cz = p[2];
        if (tid == 0) g_fps[b*NS] = 0;
        __syncthreads();

        for (int s = 1; s < NS; ++s){
            uint64_t CX2 = pack2(cx, cx), CY2 = pack2(cy, cy), CZ2 = pack2(cz, cz);
#pragma unroll
            for (int q = 0; q < 2; ++q){
                uint64_t dx, dy, dz, xx, yy, zz, ss;
                SUB2(dx, PX[q], CX2);
                SUB2(dy, PY[q], CY2);
                SUB2(dz, PZ[q], CZ2);
                MUL2(xx, dx, dx);
                MUL2(yy, dy, dy);
                MUL2(zz, dz, dz);
                ADD2(ss, xx, yy);
                ADD2(ss, ss, zz);
                float d0, d1; unpack2(ss, d0, d1);
                md[2*q]   = fminf(md[2*q],   d0);
                md[2*q+1] = fminf(md[2*q+1], d1);
            }
            float tv = fmaxf(fmaxf(md[0], md[1]), fmaxf(md[2], md[3]));

            unsigned wv = __reduce_max_sync(FULL, __float_as_uint(tv));
            unsigned mi = 0xFFFFFFFFu;
#pragma unroll
            for (int j = 0; j < 4; ++j){
                unsigned gi = (unsigned)(tid + j*1024);
                if (__float_as_uint(md[j]) == wv) mi = min(mi, gi);
            }
            unsigned wi = __reduce_min_sync(FULL, mi);

            int par = s & 1;
            if (lane == 0){ sv[par][w] = wv; si[par][w] = wi; }
            __syncthreads();

            unsigned lv = sv[par][lane];
            unsigned gv = __reduce_max_sync(FULL, lv);
            unsigned cand = (lv == gv) ? si[par][lane] : 0xFFFFFFFFu;
            unsigned gidx = __reduce_min_sync(FULL, cand);

            if (tid == 0){
                g_fps[b*NS + s] = (int)gidx;
                if ((s & 3) == 3) st_rel(&g_prog[b], s + 1);   // publish every 4
            }
            cx = p[gidx*3+0]; cy = p[gidx*3+1]; cz = p[gidx*3+2];
        }
        __syncthreads();
    }

    // ======================= consumer: all blocks =======================
    // stage weights (transpose + tf32-round) + biases
    for (int i = tid; i < 67*HDIM; i += 1024){
        int k = i >> 7, n = i & 127;
        W1s[n*S1 + k] = rna_tf32(W1[i]);
    }
    for (int i = tid; i < 128*5; i += 1024){          // zero pad k=67..71
        int n = i / 5, k = 67 + i % 5;
        W1s[n*S1 + k] = 0.f;
    }
    for (int i = tid; i < HDIM*HDIM; i += 1024){
        int k = i >> 7, n = i & 127;
        W2s[n*S2 + k] = rna_tf32(W2[i]);
    }
    if (tid < 128){ bbs[tid] = b1[tid]; bbs[128 + tid] = b2[tid]; }
    if (tid < 256) aggU[tid] = 0u;

    int g = lane >> 2, tg = lane & 3;
    int warpR = (w >> 2) * 16;     // 8 row-groups of 16 rows
    int warpC = (w & 3) * 32;      // 4 column blocks
    int center = warpR >> 6;       // 0 or 1
    __syncthreads();

    for (;;){
        if (tid == 0) s_tile = atomicAdd(&g_tile_ctr, 1);
        __syncthreads();
        int ticket = s_tile;
        if (ticket >= NTILES) break;
        int cloud = ticket & 7, pair = ticket >> 3;
        int c0 = cloud*NS + pair*2;

        // wait until both centers of this tile exist
        if (tid == 0){
            int need = pair*2 + 2, bo = 32;
            while (ld_acq(&g_prog[cloud]) < need){
                __nanosleep(bo);
                if (bo < 1024) bo <<= 1;
            }
        }
        __syncthreads();

        const float* p = pos + (size_t)cloud * NPER * 3;
        size_t base = (size_t)cloud * NPER;

        // ---- inlined select: 2 groups of 512 threads, one center each ----
        int grp = tid >> 9, lt = tid & 511;
        int ci = c0 + grp;
        int cidx = g_fps[ci];
        float cx = p[cidx*3+0], cy = p[cidx*3+1], cz = p[cidx*3+2];
        float* cdg = A2s + grp*CAP;
        int*   cig = ((int*)A2s) + 2*CAP + grp*CAP;
        if (lt == 0) s_cnt[grp] = 0;
        __syncthreads();

        for (int i = lt; i < NPER; i += 512){
            float d = dist2(p[i*3+0], p[i*3+1], p[i*3+2], cx, cy, cz);
            if (d <= R2){
                int q = atomicAdd(&s_cnt[grp], 1);
                if (q < CAP){ cdg[q] = d; cig[q] = i; }
            }
        }
        __syncthreads();
        int m = min(s_cnt[grp], CAP);
        if (m <= KNBR){
            for (int j = lt; j < m; j += 512) s_nb[grp][j] = cig[j];
            if (lt == 0) s_M[grp] = m;
        } else {
            for (int j = lt; j < m; j += 512){
                float dj = cdg[j]; int ij = cig[j];
                int r = 0;
                for (int u = 0; u < m; ++u){
                    float du = cdg[u];
                    r += (du < dj) || (du == dj && cig[u] < ij);
                }
                if (r < KNBR) s_nb[grp][r] = ij;
            }
            if (lt == 0) s_M[grp] = KNBR;
        }
        if (lt == 0 && out_size >= NCTR*HDIM + NCTR*3 + NCTR){
            float* po = out + NCTR*HDIM;
            po[ci*3+0] = cx; po[ci*3+1] = cy; po[ci*3+2] = cz;
            out[NCTR*HDIM + NCTR*3 + ci] = (float)cloud;
        }
        __syncthreads();
        int M0 = s_M[0], M1 = s_M[1];

        // ---- gather A1 [128 x 72] (tf32-rounded, zero-padded); 8 thr/row ----
        {
            int r = tid >> 3, q = tid & 7;
            int rg = r >> 6; int sl = r & 63;
            int M = rg ? M1 : M0;
            bool v = sl < M;
            float* arow = A1s + r*S1;
            const float4* xr = nullptr;
            int gl = 0;
            if (v){
                gl = s_nb[rg][sl];
                xr = (const float4*)(x + (base + gl)*CIN);
            }
            float4 t = v ? xr[q] : make_float4(0,0,0,0);
            t.x = rna_tf32(t.x); t.y = rna_tf32(t.y);
            t.z = rna_tf32(t.z); t.w = rna_tf32(t.w);
            *(float4*)(arow + 4*q) = t;
            t = v ? xr[q+8] : make_float4(0,0,0,0);
            t.x = rna_tf32(t.x); t.y = rna_tf32(t.y);
            t.z = rna_tf32(t.z); t.w = rna_tf32(t.w);
            *(float4*)(arow + 4*q + 32) = t;
            if (q == 0){
                float4 d4 = make_float4(0,0,0,0);
                if (v){
                    const float* pr = p + gl*3;
                    const float* pc = p + g_fps[c0 + rg]*3;
                    d4.x = rna_tf32(pr[0] - pc[0]);
                    d4.y = rna_tf32(pr[1] - pc[1]);
                    d4.z = rna_tf32(pr[2] - pc[2]);
                }
                *(float4*)(arow + 64) = d4;
            } else if (q == 1){
                *(float4*)(arow + 68) = make_float4(0,0,0,0);
            }
        }
        __syncthreads();

        // ---- GEMM1: [128x72] @ W1T -> relu+round -> A2 ----
        float acc[4][4];
#pragma unroll
        for (int nt = 0; nt < 4; ++nt)
#pragma unroll
            for (int i = 0; i < 4; ++i) acc[nt][i] = 0.f;
        gemm_tile16<9, S1, S1>(A1s, W1s, warpR, warpC, g, tg, acc);

        {
            int r0 = warpR + g;
#pragma unroll
            for (int nt = 0; nt < 4; ++nt){
                int cc = warpC + nt*8 + 2*tg;
                float ba = bbs[cc], bb = bbs[cc+1];
                float* d = acc[nt];
                float2 h0, h1;
                h0.x = rna_tf32(fmaxf(d[0] + ba, 0.f));
                h0.y = rna_tf32(fmaxf(d[1] + bb, 0.f));
                h1.x = rna_tf32(fmaxf(d[2] + ba, 0.f));
                h1.y = rna_tf32(fmaxf(d[3] + bb, 0.f));
                *(float2*)&A2s[r0*S2 + cc]     = h0;
                *(float2*)&A2s[(r0+8)*S2 + cc] = h1;
            }
        }
        __syncthreads();

        // ---- GEMM2: [128x128] @ W2T, fused relu + masked max ----
#pragma unroll
        for (int nt = 0; nt < 4; ++nt)
#pragma unroll
            for (int i = 0; i < 4; ++i) acc[nt][i] = 0.f;
        gemm_tile16<16, S2, S2>(A2s, W2s, warpR, warpC, g, tg, acc);

        {
            int M = center ? M1 : M0;
            int rIn = (warpR & 63) + g;
            bool v0 = rIn < M, v1 = (rIn + 8) < M;
            float cm[8];
#pragma unroll
            for (int i = 0; i < 8; ++i) cm[i] = 0.f;   // valid contributions are >= 0
#pragma unroll
            for (int nt = 0; nt < 4; ++nt){
                int cc = warpC + nt*8 + 2*tg;
                float ba = bbs[128+cc], bb = bbs[128+cc+1];
                float* d = acc[nt];
                if (v0){
                    cm[nt*2]   = fmaxf(cm[nt*2],   fmaxf(d[0] + ba, 0.f));
                    cm[nt*2+1] = fmaxf(cm[nt*2+1], fmaxf(d[1] + bb, 0.f));
                }
                if (v1){
                    cm[nt*2]   = fmaxf(cm[nt*2],   fmaxf(d[2] + ba, 0.f));
                    cm[nt*2+1] = fmaxf(cm[nt*2+1], fmaxf(d[3] + bb, 0.f));
                }
            }
#pragma unroll
            for (int o = 16; o >= 4; o >>= 1)
#pragma unroll
                for (int i = 0; i < 8; ++i)
                    cm[i] = fmaxf(cm[i], __shfl_down_sync(FULL, cm[i], o));
            if (lane < 4){       // g==0 lanes hold warp-level col maxima (tg=lane)
#pragma unroll
                for (int nt = 0; nt < 4; ++nt){
                    int cc = warpC + nt*8 + 2*lane;
                    atomicMax(&aggU[center*128 + cc],     __float_as_uint(cm[nt*2]));
                    atomicMax(&aggU[center*128 + cc + 1], __float_as_uint(cm[nt*2+1]));
                }
            }
        }
        __syncthreads();

        if (tid < 256){
            int cen = tid >> 7, col = tid & 127;
            out[(size_t)(c0 + cen)*HDIM + col] = __uint_as_float(aggU[tid]);
            aggU[tid] = 0u;      // reset for next ticket (same thread -> no race)
        }
    }
}

// ---------------------------------------------------------------------------
extern "C" void kernel_launch(void* const* d_in, const int* in_sizes, int n_in,
                              void* d_out, int out_size){
    const float *x = 0, *pos = 0, *W1 = 0, *b1 = 0, *W2 = 0, *b2 = 0;
    for (int i = 0; i < n_in; ++i){
        int s = in_sizes[i];
        const float* p = (const float*)d_in[i];
        if      (s == NB*NPER*CIN)  x   = p;
        else if (s == NB*NPER*3)    pos = p;
        else if (s == 67*HDIM)      W1  = p;
        else if (s == HDIM*HDIM)    W2  = p;
        else if (s == HDIM){ if (!b1) b1 = p; else b2 = p; }
    }
    float* out = (float*)d_out;

    size_t smem = SMEM_FLOATS * sizeof(float);
    cudaFuncSetAttribute(fused_kernel, cudaFuncAttributeMaxDynamicSharedMemorySize, (int)smem);

    init_kernel<<<1, 32>>>();
    fused_kernel<<<148, 1024, smem>>>(x, pos, W1, b1, W2, b2, out, out_size);
}